// round 2
// baseline (speedup 1.0000x reference)
#include <cuda_runtime.h>
#include <cuda_fp16.h>
#include <mma.h>
#include <cstdint>
#include <cstddef>

using namespace nvcuda;

// ---------------- problem constants ----------------
#define Dc     1024
#define DFFc   4096
#define Ec     16
#define TKc    4
#define STEPSc 4
#define Tc     2048
#define RMAXc  (Tc*TKc)              // 8192 max assignments/step
#define PEREXP (DFFc*Dc)             // 4194304 weights per expert tensor

// ---------------- device scratch (static, allowed) ----------------
__device__ __half g_w1q[(size_t)Ec*DFFc*Dc];   // ternary fp16, 128MB
__device__ __half g_w2q[(size_t)Ec*DFFc*Dc];   // 128MB
__device__ float  g_gateq[Ec*Dc];              // ternary gate (scale-free)
__device__ float  g_g1[Ec];
__device__ float  g_g2[Ec];
__device__ float  g_part[32*1024];             // reduction partials
__device__ float  g_state[Tc*Dc];              // fp32 state, 8MB
__device__ __half g_ctx_hi[Tc*Dc];             // fp16 context hi
__device__ __half g_ctx_lo[Tc*Dc];             // fp16 context lo (residual)
__device__ __half g_h_hi[(size_t)RMAXc*DFFc];  // gelu'd hidden hi, 64MB
__device__ __half g_h_lo[(size_t)RMAXc*DFFc];  // gelu'd hidden lo, 64MB
__device__ float  g_osl[(size_t)RMAXc*Dc];     // per-slot FFN2 out fp32, 32MB
__device__ int    g_list[Ec*Tc];               // per-expert slot codes (tok*4+k)
__device__ int    g_sel[Tc*TKc];               // per-token selected experts
__device__ int    g_cnt[Ec];
__device__ int    g_off[Ec];

// ---------------- small utility kernels ----------------
__global__ void copy_in_kernel(const float* __restrict__ x) {
    int i = blockIdx.x * blockDim.x + threadIdx.x;
    if (i < Tc*Dc) g_state[i] = x[i];
}
__global__ void copy_out_kernel(float* __restrict__ out) {
    int i = blockIdx.x * blockDim.x + threadIdx.x;
    if (i < Tc*Dc) out[i] = g_state[i];
}
__global__ void zero_cnt_kernel() { if (threadIdx.x < Ec) g_cnt[threadIdx.x] = 0; }

__global__ void offsets_kernel() {
    if (threadIdx.x == 0) {
        int r = 0;
        for (int e = 0; e < Ec; e++) { g_off[e] = r; r += g_cnt[e]; }
    }
}

// ---------------- quantization: abs-mean reductions (deterministic trees) ----------------
__global__ void abs_partial_kernel(const float* __restrict__ w1, const float* __restrict__ w2) {
    int chunk = blockIdx.x;            // 0..1023 (4096 elems each)
    int tn    = blockIdx.y;            // 0..31   (16 w1 tensors, 16 w2 tensors)
    const float* base = (tn < Ec) ? (w1 + (size_t)tn * PEREXP)
                                  : (w2 + (size_t)(tn - Ec) * PEREXP);
    base += (size_t)chunk * 4096;
    int tid = threadIdx.x;
    float s = 0.f;
    #pragma unroll
    for (int i = 0; i < 16; i++) s += fabsf(base[tid + i*256]);
    __shared__ float red[256];
    red[tid] = s; __syncthreads();
    for (int st = 128; st > 0; st >>= 1) { if (tid < st) red[tid] += red[tid+st]; __syncthreads(); }
    if (tid == 0) g_part[tn*1024 + chunk] = red[0];
}

__global__ void scales_kernel() {
    int tn = blockIdx.x;               // 0..31
    int tid = threadIdx.x;
    float s = 0.f;
    for (int i = tid; i < 1024; i += 256) s += g_part[tn*1024 + i];
    __shared__ float red[256];
    red[tid] = s; __syncthreads();
    for (int st = 128; st > 0; st >>= 1) { if (tid < st) red[tid] += red[tid+st]; __syncthreads(); }
    if (tid == 0) {
        float g = fmaxf(red[0] / (float)PEREXP, 1e-5f);
        if (tn < Ec) g_g1[tn] = g; else g_g2[tn - Ec] = g;
    }
}

__global__ void gate_kernel(const float* __restrict__ gw) {
    int tid = threadIdx.x;
    float s = 0.f;
    for (int i = tid; i < Ec*Dc; i += 256) s += fabsf(gw[i]);
    __shared__ float red[256];
    __shared__ float sg;
    red[tid] = s; __syncthreads();
    for (int st = 128; st > 0; st >>= 1) { if (tid < st) red[tid] += red[tid+st]; __syncthreads(); }
    if (tid == 0) sg = fmaxf(red[0] / (float)(Ec*Dc), 1e-5f);
    __syncthreads();
    float g = sg;
    // scale-free ternary gate: ordering of logits unaffected by positive scale
    for (int i = tid; i < Ec*Dc; i += 256) {
        float q = rintf(gw[i] / g);
        g_gateq[i] = fminf(fmaxf(q, -1.f), 1.f);
    }
}

__global__ void quantw_kernel(const float* __restrict__ w, int which) {
    __half* q = which ? g_w2q : g_w1q;
    const float* gs = which ? g_g2 : g_g1;
    size_t nvec   = (size_t)Ec * PEREXP / 4;
    size_t stride = (size_t)gridDim.x * blockDim.x;
    for (size_t i = (size_t)blockIdx.x * blockDim.x + threadIdx.x; i < nvec; i += stride) {
        int e = (int)((i * 4) / (size_t)PEREXP);
        float g = gs[e];
        float4 v = reinterpret_cast<const float4*>(w)[i];
        float q0 = fminf(fmaxf(rintf(v.x / g), -1.f), 1.f);
        float q1 = fminf(fmaxf(rintf(v.y / g), -1.f), 1.f);
        float q2 = fminf(fmaxf(rintf(v.z / g), -1.f), 1.f);
        float q3 = fminf(fmaxf(rintf(v.w / g), -1.f), 1.f);
        __half2* qo = reinterpret_cast<__half2*>(q) + i*2;
        qo[0] = __floats2half2_rn(q0, q1);
        qo[1] = __floats2half2_rn(q2, q3);
    }
}

// ---------------- routing: ctx = state + temb, ternary logits, top-4 ----------------
__global__ void route_kernel(const float* __restrict__ comp, const float* __restrict__ temb, int step) {
    int t = blockIdx.x, tid = threadIdx.x;
    if (!(comp[t] > 0.5f)) {
        // masked tokens: state never updates -> skip compute, but keep ctx well-defined
        #pragma unroll
        for (int i = 0; i < 8; i++) {
            int d = tid + i*128;
            g_ctx_hi[t*Dc + d] = __float2half(0.f);
            g_ctx_lo[t*Dc + d] = __float2half(0.f);
        }
        return;
    }
    float cx[8];
    #pragma unroll
    for (int i = 0; i < 8; i++) {
        int d = tid + i*128;
        float v = g_state[t*Dc + d] + temb[step*Dc + d];
        cx[i] = v;
        __half hi = __float2half(v);
        g_ctx_hi[t*Dc + d] = hi;
        g_ctx_lo[t*Dc + d] = __float2half(v - __half2float(hi));
    }
    float p[16];
    #pragma unroll
    for (int e = 0; e < 16; e++) p[e] = 0.f;
    #pragma unroll
    for (int i = 0; i < 8; i++) {
        int d = tid + i*128;
        #pragma unroll
        for (int e = 0; e < 16; e++) p[e] += cx[i] * g_gateq[e*Dc + d];
    }
    __shared__ float wsum[4][16];
    __shared__ float slog[16];
    int lane = tid & 31, wp = tid >> 5;
    #pragma unroll
    for (int e = 0; e < 16; e++) {
        float s = p[e];
        for (int o = 16; o > 0; o >>= 1) s += __shfl_down_sync(0xffffffffu, s, o);
        if (lane == 0) wsum[wp][e] = s;
    }
    __syncthreads();
    if (tid < 16) slog[tid] = wsum[0][tid] + wsum[1][tid] + wsum[2][tid] + wsum[3][tid];
    __syncthreads();
    if (tid == 0) {
        float lg[16];
        #pragma unroll
        for (int e = 0; e < 16; e++) lg[e] = slog[e];
        for (int k = 0; k < TKc; k++) {
            int best = 0; float bv = lg[0];
            for (int e = 1; e < 16; e++) if (lg[e] > bv) { bv = lg[e]; best = e; }  // ties -> lowest idx
            g_sel[t*TKc + k] = best;
            lg[best] = -3.4e38f;
            int pos = atomicAdd(&g_cnt[best], 1);
            g_list[best*Tc + pos] = t*TKc + k;
        }
    }
}

// ---------------- FFN1: H[r,:] = gelu(g1 * ctx[tok] @ W1t[e]^T), split fp16 wmma ----------------
__global__ void ffn1_kernel() {
    int e   = blockIdx.z;
    int cnt = g_cnt[e];
    int m0  = blockIdx.x * 64;
    if (m0 >= cnt) return;
    int n0  = blockIdx.y * 64;
    __shared__ __align__(16) __half AsHi[64][72];
    __shared__ __align__(16) __half AsLo[64][72];
    __shared__ __align__(16) float  Cs[64][68];
    __shared__ int rows[64];
    int tid = threadIdx.x;
    if (tid < 64) rows[tid] = (m0 + tid < cnt) ? g_list[e*Tc + m0 + tid] : -1;
    __syncthreads();
    int warp = tid >> 5;
    int wm = warp & 3, wn = warp >> 2;   // 4x2 warp grid, warp tile 16x32
    wmma::fragment<wmma::accumulator,16,16,16,float> acc0, acc1;
    wmma::fill_fragment(acc0, 0.f);
    wmma::fill_fragment(acc1, 0.f);
    const __half* W = g_w1q + (size_t)e*DFFc*Dc + (size_t)(n0 + wn*32)*Dc;
    for (int k0 = 0; k0 < Dc; k0 += 64) {
        #pragma unroll
        for (int it = 0; it < 2; it++) {
            int chunk = tid + it*256;
            int r = chunk >> 3, c = (chunk & 7) << 3;
            int code = rows[r];
            int tok = code >= 0 ? (code >> 2) : 0;
            *reinterpret_cast<uint4*>(&AsHi[r][c]) =
                *reinterpret_cast<const uint4*>(&g_ctx_hi[(size_t)tok*Dc + k0 + c]);
            *reinterpret_cast<uint4*>(&AsLo[r][c]) =
                *reinterpret_cast<const uint4*>(&g_ctx_lo[(size_t)tok*Dc + k0 + c]);
        }
        __syncthreads();
        #pragma unroll
        for (int kk = 0; kk < 64; kk += 16) {
            wmma::fragment<wmma::matrix_a,16,16,16,__half,wmma::row_major> aHi, aLo;
            wmma::load_matrix_sync(aHi, &AsHi[wm*16][kk], 72);
            wmma::load_matrix_sync(aLo, &AsLo[wm*16][kk], 72);
            wmma::fragment<wmma::matrix_b,16,16,16,__half,wmma::col_major> b;
            wmma::load_matrix_sync(b, W + (size_t)(k0 + kk), Dc);
            wmma::mma_sync(acc0, aHi, b, acc0);
            wmma::mma_sync(acc0, aLo, b, acc0);
            wmma::load_matrix_sync(b, W + (size_t)16*Dc + k0 + kk, Dc);
            wmma::mma_sync(acc1, aHi, b, acc1);
            wmma::mma_sync(acc1, aLo, b, acc1);
        }
        __syncthreads();
    }
    wmma::store_matrix_sync(&Cs[wm*16][wn*32],      acc0, 68, wmma::mem_row_major);
    wmma::store_matrix_sync(&Cs[wm*16][wn*32 + 16], acc1, 68, wmma::mem_row_major);
    __syncthreads();
    float g1 = g_g1[e];
    int off  = g_off[e];
    for (int idx = tid; idx < 64*64; idx += 256) {
        int r = idx >> 6, c = idx & 63;
        if (rows[r] < 0) continue;
        float v  = g1 * Cs[r][c];
        float ge = 0.5f * v * (1.0f + erff(v * 0.7071067811865476f));  // exact GELU
        __half hi = __float2half(ge);
        size_t o  = (size_t)(off + m0 + r)*DFFc + n0 + c;
        g_h_hi[o] = hi;
        g_h_lo[o] = __float2half(ge - __half2float(hi));
    }
}

// ---------------- FFN2: O[slot,:] = g2 * H[r] @ W2t[e]^T, split fp16 wmma ----------------
__global__ void ffn2_kernel() {
    int e   = blockIdx.z;
    int cnt = g_cnt[e];
    int m0  = blockIdx.x * 64;
    if (m0 >= cnt) return;
    int n0  = blockIdx.y * 64;
    __shared__ __align__(16) __half AsHi[64][72];
    __shared__ __align__(16) __half AsLo[64][72];
    __shared__ __align__(16) float  Cs[64][68];
    __shared__ int slots[64];
    int tid = threadIdx.x;
    int off = g_off[e];
    if (tid < 64) slots[tid] = (m0 + tid < cnt) ? g_list[e*Tc + m0 + tid] : -1;
    __syncthreads();
    int warp = tid >> 5;
    int wm = warp & 3, wn = warp >> 2;
    wmma::fragment<wmma::accumulator,16,16,16,float> acc0, acc1;
    wmma::fill_fragment(acc0, 0.f);
    wmma::fill_fragment(acc1, 0.f);
    const __half* W = g_w2q + (size_t)e*DFFc*Dc + (size_t)(n0 + wn*32)*DFFc;
    int lastrow = off + cnt - 1;
    for (int k0 = 0; k0 < DFFc; k0 += 64) {
        #pragma unroll
        for (int it = 0; it < 2; it++) {
            int chunk = tid + it*256;
            int r = chunk >> 3, c = (chunk & 7) << 3;
            int src = off + m0 + r;
            if (src > lastrow) src = lastrow;   // clamp: read valid data, never stored
            *reinterpret_cast<uint4*>(&AsHi[r][c]) =
                *reinterpret_cast<const uint4*>(&g_h_hi[(size_t)src*DFFc + k0 + c]);
            *reinterpret_cast<uint4*>(&AsLo[r][c]) =
                *reinterpret_cast<const uint4*>(&g_h_lo[(size_t)src*DFFc + k0 + c]);
        }
        __syncthreads();
        #pragma unroll
        for (int kk = 0; kk < 64; kk += 16) {
            wmma::fragment<wmma::matrix_a,16,16,16,__half,wmma::row_major> aHi, aLo;
            wmma::load_matrix_sync(aHi, &AsHi[wm*16][kk], 72);
            wmma::load_matrix_sync(aLo, &AsLo[wm*16][kk], 72);
            wmma::fragment<wmma::matrix_b,16,16,16,__half,wmma::col_major> b;
            wmma::load_matrix_sync(b, W + (size_t)(k0 + kk), DFFc);
            wmma::mma_sync(acc0, aHi, b, acc0);
            wmma::mma_sync(acc0, aLo, b, acc0);
            wmma::load_matrix_sync(b, W + (size_t)16*DFFc + k0 + kk, DFFc);
            wmma::mma_sync(acc1, aHi, b, acc1);
            wmma::mma_sync(acc1, aLo, b, acc1);
        }
        __syncthreads();
    }
    wmma::store_matrix_sync(&Cs[wm*16][wn*32],      acc0, 68, wmma::mem_row_major);
    wmma::store_matrix_sync(&Cs[wm*16][wn*32 + 16], acc1, 68, wmma::mem_row_major);
    __syncthreads();
    float g2 = g_g2[e];
    for (int idx = tid; idx < 64*64; idx += 256) {
        int r = idx >> 6, c = idx & 63;
        int sc = slots[r];
        if (sc < 0) continue;
        g_osl[(size_t)sc*Dc + n0 + c] = g2 * Cs[r][c];
    }
}

// ---------------- combine: slot-sum (expert-ascending) + residual + RMSNorm ----------------
__global__ void combine_kernel(const float* __restrict__ comp, const float* __restrict__ normw) {
    int t = blockIdx.x, tid = threadIdx.x;
    if (!(comp[t] > 0.5f)) return;     // masked: state unchanged
    int se[4];
    #pragma unroll
    for (int k = 0; k < 4; k++) se[k] = g_sel[t*4 + k];
    int ord[4] = {0,1,2,3};
    #pragma unroll
    for (int a = 0; a < 3; a++)
        #pragma unroll
        for (int b = a+1; b < 4; b++)
            if (se[ord[b]] < se[ord[a]]) { int tmp = ord[a]; ord[a] = ord[b]; ord[b] = tmp; }
    float y[4]; float ss = 0.f;
    #pragma unroll
    for (int i = 0; i < 4; i++) {
        int d = tid + i*256;
        float s = g_osl[(size_t)(t*4 + ord[0])*Dc + d];    // expert-ascending: matches ref fp order
        s += g_osl[(size_t)(t*4 + ord[1])*Dc + d];
        s += g_osl[(size_t)(t*4 + ord[2])*Dc + d];
        s += g_osl[(size_t)(t*4 + ord[3])*Dc + d];
        float v = s + g_state[t*Dc + d];
        y[i] = v; ss += v*v;
    }
    int lane = tid & 31, wp = tid >> 5;
    for (int o = 16; o > 0; o >>= 1) ss += __shfl_down_sync(0xffffffffu, ss, o);
    __shared__ float ws[8];
    __shared__ float svar;
    if (lane == 0) ws[wp] = ss;
    __syncthreads();
    if (tid == 0) {
        float s2 = 0.f;
        for (int w = 0; w < 8; w++) s2 += ws[w];
        svar = s2 * (1.f / (float)Dc);
    }
    __syncthreads();
    float rinv = rsqrtf(svar + 1e-6f);
    #pragma unroll
    for (int i = 0; i < 4; i++) {
        int d = tid + i*256;
        g_state[t*Dc + d] = normw[d] * y[i] * rinv;
    }
}

// ---------------- launch ----------------
extern "C" void kernel_launch(void* const* d_in, const int* in_sizes, int n_in,
                              void* d_out, int out_size) {
    const float* x    = (const float*)d_in[0];
    const float* comp = (const float*)d_in[1];
    const float* gw   = (const float*)d_in[2];
    const float* w1   = (const float*)d_in[3];
    const float* w2   = (const float*)d_in[4];
    const float* temb = (const float*)d_in[5];
    const float* nw   = (const float*)d_in[6];
    float* out = (float*)d_out;

    copy_in_kernel<<<(Tc*Dc + 511)/512, 512>>>(x);

    abs_partial_kernel<<<dim3(1024, 32), 256>>>(w1, w2);
    scales_kernel<<<32, 256>>>();
    gate_kernel<<<1, 256>>>(gw);
    quantw_kernel<<<8192, 256>>>(w1, 0);
    quantw_kernel<<<8192, 256>>>(w2, 1);

    for (int s = 0; s < STEPSc; s++) {
        zero_cnt_kernel<<<1, 32>>>();
        route_kernel<<<Tc, 128>>>(comp, temb, s);
        offsets_kernel<<<1, 32>>>();
        ffn1_kernel<<<dim3(32, DFFc/64, Ec), 256>>>();
        ffn2_kernel<<<dim3(32, Dc/64, Ec), 256>>>();
        combine_kernel<<<Tc, 256>>>(comp, nw);
    }

    copy_out_kernel<<<(Tc*Dc + 511)/512, 512>>>(out);
}

// round 3
// speedup vs baseline: 2.7654x; 2.7654x over previous
#include <cuda_runtime.h>
#include <cuda_fp16.h>
#include <mma.h>
#include <cstdint>
#include <cstddef>

using namespace nvcuda;

// ---------------- problem constants ----------------
#define Dc     1024
#define DFFc   4096
#define Ec     16
#define TKc    4
#define STEPSc 4
#define Tc     2048
#define RMAXc  (Tc*TKc)
#define PEREXP (DFFc*Dc)

// ---------------- device scratch ----------------
__device__ __half g_w1q[(size_t)Ec*DFFc*Dc];
__device__ __half g_w2q[(size_t)Ec*DFFc*Dc];
__device__ float  g_gateq[Ec*Dc];
__device__ float  g_g1[Ec];
__device__ float  g_g2[Ec];
__device__ float  g_part[32*1024];
__device__ float  g_state[Tc*Dc];
__device__ __half g_ctx_hi[Tc*Dc];
__device__ __half g_ctx_lo[Tc*Dc];
__device__ __half g_h_hi[(size_t)RMAXc*DFFc];
__device__ __half g_h_lo[(size_t)RMAXc*DFFc];
__device__ float  g_osl[(size_t)RMAXc*Dc];
__device__ int    g_list[Ec*Tc];
__device__ int    g_sel[Tc*TKc];
__device__ int    g_cnt[Ec];
__device__ int    g_off[Ec];

// ---------------- small utility kernels ----------------
__global__ void copy_in_kernel(const float* __restrict__ x) {
    int i = blockIdx.x * blockDim.x + threadIdx.x;
    if (i < Tc*Dc) g_state[i] = x[i];
}
__global__ void copy_out_kernel(float* __restrict__ out) {
    int i = blockIdx.x * blockDim.x + threadIdx.x;
    if (i < Tc*Dc) out[i] = g_state[i];
}
__global__ void zero_cnt_kernel() { if (threadIdx.x < Ec) g_cnt[threadIdx.x] = 0; }

__global__ void offsets_kernel() {
    if (threadIdx.x == 0) {
        int r = 0;
        for (int e = 0; e < Ec; e++) { g_off[e] = r; r += g_cnt[e]; }
    }
}

// ---------------- quantization ----------------
__global__ void abs_partial_kernel(const float* __restrict__ w1, const float* __restrict__ w2) {
    int chunk = blockIdx.x;
    int tn    = blockIdx.y;
    const float* base = (tn < Ec) ? (w1 + (size_t)tn * PEREXP)
                                  : (w2 + (size_t)(tn - Ec) * PEREXP);
    base += (size_t)chunk * 4096;
    int tid = threadIdx.x;
    float s = 0.f;
    #pragma unroll
    for (int i = 0; i < 16; i++) s += fabsf(base[tid + i*256]);
    __shared__ float red[256];
    red[tid] = s; __syncthreads();
    for (int st = 128; st > 0; st >>= 1) { if (tid < st) red[tid] += red[tid+st]; __syncthreads(); }
    if (tid == 0) g_part[tn*1024 + chunk] = red[0];
}

__global__ void scales_kernel() {
    int tn = blockIdx.x;
    int tid = threadIdx.x;
    float s = 0.f;
    for (int i = tid; i < 1024; i += 256) s += g_part[tn*1024 + i];
    __shared__ float red[256];
    red[tid] = s; __syncthreads();
    for (int st = 128; st > 0; st >>= 1) { if (tid < st) red[tid] += red[tid+st]; __syncthreads(); }
    if (tid == 0) {
        float g = fmaxf(red[0] / (float)PEREXP, 1e-5f);
        if (tn < Ec) g_g1[tn] = g; else g_g2[tn - Ec] = g;
    }
}

__global__ void gate_kernel(const float* __restrict__ gw) {
    int tid = threadIdx.x;
    float s = 0.f;
    for (int i = tid; i < Ec*Dc; i += 256) s += fabsf(gw[i]);
    __shared__ float red[256];
    __shared__ float sg;
    red[tid] = s; __syncthreads();
    for (int st = 128; st > 0; st >>= 1) { if (tid < st) red[tid] += red[tid+st]; __syncthreads(); }
    if (tid == 0) sg = fmaxf(red[0] / (float)(Ec*Dc), 1e-5f);
    __syncthreads();
    float g = sg;
    for (int i = tid; i < Ec*Dc; i += 256) {
        float q = rintf(gw[i] / g);
        g_gateq[i] = fminf(fmaxf(q, -1.f), 1.f);
    }
}

__global__ void quantw_kernel(const float* __restrict__ w, int which) {
    __half* q = which ? g_w2q : g_w1q;
    const float* gs = which ? g_g2 : g_g1;
    size_t nvec   = (size_t)Ec * PEREXP / 4;
    size_t stride = (size_t)gridDim.x * blockDim.x;
    for (size_t i = (size_t)blockIdx.x * blockDim.x + threadIdx.x; i < nvec; i += stride) {
        int e = (int)((i * 4) / (size_t)PEREXP);
        float g = gs[e];
        float4 v = reinterpret_cast<const float4*>(w)[i];
        float q0 = fminf(fmaxf(rintf(v.x / g), -1.f), 1.f);
        float q1 = fminf(fmaxf(rintf(v.y / g), -1.f), 1.f);
        float q2 = fminf(fmaxf(rintf(v.z / g), -1.f), 1.f);
        float q3 = fminf(fmaxf(rintf(v.w / g), -1.f), 1.f);
        __half2* qo = reinterpret_cast<__half2*>(q) + i*2;
        qo[0] = __floats2half2_rn(q0, q1);
        qo[1] = __floats2half2_rn(q2, q3);
    }
}

// ---------------- routing ----------------
__global__ void route_kernel(const float* __restrict__ comp, const float* __restrict__ temb, int step) {
    int t = blockIdx.x, tid = threadIdx.x;
    if (!(comp[t] > 0.5f)) {
        #pragma unroll
        for (int i = 0; i < 8; i++) {
            int d = tid + i*128;
            g_ctx_hi[t*Dc + d] = __float2half(0.f);
            g_ctx_lo[t*Dc + d] = __float2half(0.f);
        }
        return;
    }
    float cx[8];
    #pragma unroll
    for (int i = 0; i < 8; i++) {
        int d = tid + i*128;
        float v = g_state[t*Dc + d] + temb[step*Dc + d];
        cx[i] = v;
        __half hi = __float2half(v);
        g_ctx_hi[t*Dc + d] = hi;
        g_ctx_lo[t*Dc + d] = __float2half(v - __half2float(hi));
    }
    float p[16];
    #pragma unroll
    for (int e = 0; e < 16; e++) p[e] = 0.f;
    #pragma unroll
    for (int i = 0; i < 8; i++) {
        int d = tid + i*128;
        #pragma unroll
        for (int e = 0; e < 16; e++) p[e] += cx[i] * g_gateq[e*Dc + d];
    }
    __shared__ float wsum[4][16];
    __shared__ float slog[16];
    int lane = tid & 31, wp = tid >> 5;
    #pragma unroll
    for (int e = 0; e < 16; e++) {
        float s = p[e];
        for (int o = 16; o > 0; o >>= 1) s += __shfl_down_sync(0xffffffffu, s, o);
        if (lane == 0) wsum[wp][e] = s;
    }
    __syncthreads();
    if (tid < 16) slog[tid] = wsum[0][tid] + wsum[1][tid] + wsum[2][tid] + wsum[3][tid];
    __syncthreads();
    if (tid == 0) {
        float lg[16];
        #pragma unroll
        for (int e = 0; e < 16; e++) lg[e] = slog[e];
        for (int k = 0; k < TKc; k++) {
            int best = 0; float bv = lg[0];
            for (int e = 1; e < 16; e++) if (lg[e] > bv) { bv = lg[e]; best = e; }
            g_sel[t*TKc + k] = best;
            lg[best] = -3.4e38f;
            int pos = atomicAdd(&g_cnt[best], 1);
            g_list[best*Tc + pos] = t*TKc + k;
        }
    }
}

// ==================================================================
// GEMM tile geometry: block = 64(M) x 128(N), K-chunk 64, 256 threads
// 8 warps in 2(M) x 4(N) grid; warp tile 32x32; split-fp16 A (hi+lo)
// SMEM staging + register-prefetch double buffering.
// ==================================================================
#define SM_AHI 0
#define SM_ALO 9216
#define SM_B   18432
#define SM_BYTES 36864            // 64*72*2 *2 + 128*72*2

// ---------------- FFN1: H = gelu(g1 * ctx @ W1^T) ----------------
__global__ void __launch_bounds__(256, 2) ffn1_kernel() {
    int e   = blockIdx.z;
    int cnt = g_cnt[e];
    int m0  = blockIdx.x * 64;
    if (m0 >= cnt) return;
    int n0  = blockIdx.y * 128;

    __shared__ __align__(16) char smem_raw[SM_BYTES];
    __shared__ int rows[64];
    __half (*AsHi)[72] = (__half(*)[72])(smem_raw + SM_AHI);
    __half (*AsLo)[72] = (__half(*)[72])(smem_raw + SM_ALO);
    __half (*Bs)[72]   = (__half(*)[72])(smem_raw + SM_B);
    float (*Cs)[132]   = (float(*)[132])(smem_raw);

    int tid = threadIdx.x;
    if (tid < 64) rows[tid] = (m0 + tid < cnt) ? g_list[e*Tc + m0 + tid] : -1;
    __syncthreads();

    int warp = tid >> 5;
    int wm = warp & 1, wn = warp >> 1;      // 2x4 warp grid
    wmma::fragment<wmma::accumulator,16,16,16,float> acc[2][2];
    #pragma unroll
    for (int i = 0; i < 2; i++)
        #pragma unroll
        for (int j = 0; j < 2; j++) wmma::fill_fragment(acc[i][j], 0.f);

    const __half* W = g_w1q + (size_t)e*DFFc*Dc + (size_t)n0*Dc;

    // per-thread stage indices (8B granule = uint4 of halves)
    int ar = tid >> 2, ac = (tid & 3) << 4;          // A: 64 rows, 2 uint4/row-half... (tid/4, (tid%3)*16)
    // A tile is 64x64 halves = 512 uint4; thread handles 2: rows tid>>2, cols (tid&3)*16 .. +8
    int tokA = rows[ar] >= 0 ? (rows[ar] >> 2) : 0;
    // B tile 128x64 halves = 1024 uint4; thread handles 4: rows (tid>>1)&127? simpler: r = tid>>1 + it*128? 
    // choose: for it in 0..3: r = (tid >> 1) + (it & 1)*... use linear: u = tid + it*256; r=u>>2, c=(u&3)*16
    uint4 pAhi[2], pAlo[2], pB[4];

    // prefetch chunk 0
    {
        int k0 = 0;
        #pragma unroll
        for (int it = 0; it < 2; it++) {
            int u = tid + it*256;            // 0..511
            int r = u >> 3, c = (u & 7) << 3;
            int tok = rows[r] >= 0 ? (rows[r] >> 2) : 0;
            pAhi[it] = *reinterpret_cast<const uint4*>(&g_ctx_hi[(size_t)tok*Dc + k0 + c]);
            pAlo[it] = *reinterpret_cast<const uint4*>(&g_ctx_lo[(size_t)tok*Dc + k0 + c]);
        }
        #pragma unroll
        for (int it = 0; it < 4; it++) {
            int u = tid + it*256;            // 0..1023
            int r = u >> 3, c = (u & 7) << 3;
            pB[it] = *reinterpret_cast<const uint4*>(&W[(size_t)r*Dc + k0 + c]);
        }
    }
    (void)tokA; (void)ar; (void)ac;

    for (int k0 = 0; k0 < Dc; k0 += 64) {
        // store prefetched regs -> smem
        #pragma unroll
        for (int it = 0; it < 2; it++) {
            int u = tid + it*256;
            int r = u >> 3, c = (u & 7) << 3;
            *reinterpret_cast<uint4*>(&AsHi[r][c]) = pAhi[it];
            *reinterpret_cast<uint4*>(&AsLo[r][c]) = pAlo[it];
        }
        #pragma unroll
        for (int it = 0; it < 4; it++) {
            int u = tid + it*256;
            int r = u >> 3, c = (u & 7) << 3;
            *reinterpret_cast<uint4*>(&Bs[r][c]) = pB[it];
        }
        __syncthreads();
        // issue prefetch for next chunk (overlaps with MMA below)
        int k1 = k0 + 64;
        if (k1 < Dc) {
            #pragma unroll
            for (int it = 0; it < 2; it++) {
                int u = tid + it*256;
                int r = u >> 3, c = (u & 7) << 3;
                int tok = rows[r] >= 0 ? (rows[r] >> 2) : 0;
                pAhi[it] = *reinterpret_cast<const uint4*>(&g_ctx_hi[(size_t)tok*Dc + k1 + c]);
                pAlo[it] = *reinterpret_cast<const uint4*>(&g_ctx_lo[(size_t)tok*Dc + k1 + c]);
            }
            #pragma unroll
            for (int it = 0; it < 4; it++) {
                int u = tid + it*256;
                int r = u >> 3, c = (u & 7) << 3;
                pB[it] = *reinterpret_cast<const uint4*>(&W[(size_t)r*Dc + k1 + c]);
            }
        }
        // compute
        #pragma unroll
        for (int kk = 0; kk < 64; kk += 16) {
            wmma::fragment<wmma::matrix_a,16,16,16,__half,wmma::row_major> aHi[2], aLo[2];
            wmma::fragment<wmma::matrix_b,16,16,16,__half,wmma::col_major> b[2];
            #pragma unroll
            for (int i = 0; i < 2; i++) {
                wmma::load_matrix_sync(aHi[i], &AsHi[wm*32 + i*16][kk], 72);
                wmma::load_matrix_sync(aLo[i], &AsLo[wm*32 + i*16][kk], 72);
            }
            #pragma unroll
            for (int j = 0; j < 2; j++)
                wmma::load_matrix_sync(b[j], &Bs[wn*32 + j*16][kk], 72);
            #pragma unroll
            for (int i = 0; i < 2; i++)
                #pragma unroll
                for (int j = 0; j < 2; j++) {
                    wmma::mma_sync(acc[i][j], aHi[i], b[j], acc[i][j]);
                    wmma::mma_sync(acc[i][j], aLo[i], b[j], acc[i][j]);
                }
        }
        __syncthreads();
    }

    // epilogue via smem
    #pragma unroll
    for (int i = 0; i < 2; i++)
        #pragma unroll
        for (int j = 0; j < 2; j++)
            wmma::store_matrix_sync(&Cs[wm*32 + i*16][wn*32 + j*16], acc[i][j], 132, wmma::mem_row_major);
    __syncthreads();

    float g1 = g_g1[e];
    int off  = g_off[e];
    for (int idx = tid; idx < 64*128; idx += 256) {
        int r = idx >> 7, c = idx & 127;
        if (rows[r] < 0) continue;
        float v  = g1 * Cs[r][c];
        float ge = 0.5f * v * (1.0f + erff(v * 0.7071067811865476f));
        __half hi = __float2half(ge);
        size_t o  = (size_t)(off + m0 + r)*DFFc + n0 + c;
        g_h_hi[o] = hi;
        g_h_lo[o] = __float2half(ge - __half2float(hi));
    }
}

// ---------------- FFN2: O = g2 * H @ W2^T ----------------
__global__ void __launch_bounds__(256, 2) ffn2_kernel() {
    int e   = blockIdx.z;
    int cnt = g_cnt[e];
    int m0  = blockIdx.x * 64;
    if (m0 >= cnt) return;
    int n0  = blockIdx.y * 128;

    __shared__ __align__(16) char smem_raw[SM_BYTES];
    __shared__ int slots[64];
    __half (*AsHi)[72] = (__half(*)[72])(smem_raw + SM_AHI);
    __half (*AsLo)[72] = (__half(*)[72])(smem_raw + SM_ALO);
    __half (*Bs)[72]   = (__half(*)[72])(smem_raw + SM_B);
    float (*Cs)[132]   = (float(*)[132])(smem_raw);

    int tid = threadIdx.x;
    int off = g_off[e];
    if (tid < 64) slots[tid] = (m0 + tid < cnt) ? g_list[e*Tc + m0 + tid] : -1;
    __syncthreads();

    int warp = tid >> 5;
    int wm = warp & 1, wn = warp >> 1;
    wmma::fragment<wmma::accumulator,16,16,16,float> acc[2][2];
    #pragma unroll
    for (int i = 0; i < 2; i++)
        #pragma unroll
        for (int j = 0; j < 2; j++) wmma::fill_fragment(acc[i][j], 0.f);

    const __half* W = g_w2q + (size_t)e*DFFc*Dc + (size_t)n0*DFFc;
    int lastrow = off + cnt - 1;

    uint4 pAhi[2], pAlo[2], pB[4];
    {
        int k0 = 0;
        #pragma unroll
        for (int it = 0; it < 2; it++) {
            int u = tid + it*256;
            int r = u >> 3, c = (u & 7) << 3;
            int src = off + m0 + r; if (src > lastrow) src = lastrow;
            pAhi[it] = *reinterpret_cast<const uint4*>(&g_h_hi[(size_t)src*DFFc + k0 + c]);
            pAlo[it] = *reinterpret_cast<const uint4*>(&g_h_lo[(size_t)src*DFFc + k0 + c]);
        }
        #pragma unroll
        for (int it = 0; it < 4; it++) {
            int u = tid + it*256;
            int r = u >> 3, c = (u & 7) << 3;
            pB[it] = *reinterpret_cast<const uint4*>(&W[(size_t)r*DFFc + k0 + c]);
        }
    }

    for (int k0 = 0; k0 < DFFc; k0 += 64) {
        #pragma unroll
        for (int it = 0; it < 2; it++) {
            int u = tid + it*256;
            int r = u >> 3, c = (u & 7) << 3;
            *reinterpret_cast<uint4*>(&AsHi[r][c]) = pAhi[it];
            *reinterpret_cast<uint4*>(&AsLo[r][c]) = pAlo[it];
        }
        #pragma unroll
        for (int it = 0; it < 4; it++) {
            int u = tid + it*256;
            int r = u >> 3, c = (u & 7) << 3;
            *reinterpret_cast<uint4*>(&Bs[r][c]) = pB[it];
        }
        __syncthreads();
        int k1 = k0 + 64;
        if (k1 < DFFc) {
            #pragma unroll
            for (int it = 0; it < 2; it++) {
                int u = tid + it*256;
                int r = u >> 3, c = (u & 7) << 3;
                int src = off + m0 + r; if (src > lastrow) src = lastrow;
                pAhi[it] = *reinterpret_cast<const uint4*>(&g_h_hi[(size_t)src*DFFc + k1 + c]);
                pAlo[it] = *reinterpret_cast<const uint4*>(&g_h_lo[(size_t)src*DFFc + k1 + c]);
            }
            #pragma unroll
            for (int it = 0; it < 4; it++) {
                int u = tid + it*256;
                int r = u >> 3, c = (u & 7) << 3;
                pB[it] = *reinterpret_cast<const uint4*>(&W[(size_t)r*DFFc + k1 + c]);
            }
        }
        #pragma unroll
        for (int kk = 0; kk < 64; kk += 16) {
            wmma::fragment<wmma::matrix_a,16,16,16,__half,wmma::row_major> aHi[2], aLo[2];
            wmma::fragment<wmma::matrix_b,16,16,16,__half,wmma::col_major> b[2];
            #pragma unroll
            for (int i = 0; i < 2; i++) {
                wmma::load_matrix_sync(aHi[i], &AsHi[wm*32 + i*16][kk], 72);
                wmma::load_matrix_sync(aLo[i], &AsLo[wm*32 + i*16][kk], 72);
            }
            #pragma unroll
            for (int j = 0; j < 2; j++)
                wmma::load_matrix_sync(b[j], &Bs[wn*32 + j*16][kk], 72);
            #pragma unroll
            for (int i = 0; i < 2; i++)
                #pragma unroll
                for (int j = 0; j < 2; j++) {
                    wmma::mma_sync(acc[i][j], aHi[i], b[j], acc[i][j]);
                    wmma::mma_sync(acc[i][j], aLo[i], b[j], acc[i][j]);
                }
        }
        __syncthreads();
    }

    #pragma unroll
    for (int i = 0; i < 2; i++)
        #pragma unroll
        for (int j = 0; j < 2; j++)
            wmma::store_matrix_sync(&Cs[wm*32 + i*16][wn*32 + j*16], acc[i][j], 132, wmma::mem_row_major);
    __syncthreads();

    float g2 = g_g2[e];
    for (int idx = tid; idx < 64*128; idx += 256) {
        int r = idx >> 7, c = idx & 127;
        int sc = slots[r];
        if (sc < 0) continue;
        g_osl[(size_t)sc*Dc + n0 + c] = g2 * Cs[r][c];
    }
}

// ---------------- combine ----------------
__global__ void combine_kernel(const float* __restrict__ comp, const float* __restrict__ normw) {
    int t = blockIdx.x, tid = threadIdx.x;
    if (!(comp[t] > 0.5f)) return;
    int se[4];
    #pragma unroll
    for (int k = 0; k < 4; k++) se[k] = g_sel[t*4 + k];
    int ord[4] = {0,1,2,3};
    #pragma unroll
    for (int a = 0; a < 3; a++)
        #pragma unroll
        for (int b = a+1; b < 4; b++)
            if (se[ord[b]] < se[ord[a]]) { int tmp = ord[a]; ord[a] = ord[b]; ord[b] = tmp; }
    float y[4]; float ss = 0.f;
    #pragma unroll
    for (int i = 0; i < 4; i++) {
        int d = tid + i*256;
        float s = g_osl[(size_t)(t*4 + ord[0])*Dc + d];
        s += g_osl[(size_t)(t*4 + ord[1])*Dc + d];
        s += g_osl[(size_t)(t*4 + ord[2])*Dc + d];
        s += g_osl[(size_t)(t*4 + ord[3])*Dc + d];
        float v = s + g_state[t*Dc + d];
        y[i] = v; ss += v*v;
    }
    int lane = tid & 31, wp = tid >> 5;
    for (int o = 16; o > 0; o >>= 1) ss += __shfl_down_sync(0xffffffffu, ss, o);
    __shared__ float ws[8];
    __shared__ float svar;
    if (lane == 0) ws[wp] = ss;
    __syncthreads();
    if (tid == 0) {
        float s2 = 0.f;
        for (int w = 0; w < 8; w++) s2 += ws[w];
        svar = s2 * (1.f / (float)Dc);
    }
    __syncthreads();
    float rinv = rsqrtf(svar + 1e-6f);
    #pragma unroll
    for (int i = 0; i < 4; i++) {
        int d = tid + i*256;
        g_state[t*Dc + d] = normw[d] * y[i] * rinv;
    }
}

// ---------------- launch ----------------
extern "C" void kernel_launch(void* const* d_in, const int* in_sizes, int n_in,
                              void* d_out, int out_size) {
    const float* x    = (const float*)d_in[0];
    const float* comp = (const float*)d_in[1];
    const float* gw   = (const float*)d_in[2];
    const float* w1   = (const float*)d_in[3];
    const float* w2   = (const float*)d_in[4];
    const float* temb = (const float*)d_in[5];
    const float* nw   = (const float*)d_in[6];
    float* out = (float*)d_out;

    copy_in_kernel<<<(Tc*Dc + 511)/512, 512>>>(x);

    abs_partial_kernel<<<dim3(1024, 32), 256>>>(w1, w2);
    scales_kernel<<<32, 256>>>();
    gate_kernel<<<1, 256>>>(gw);
    quantw_kernel<<<8192, 256>>>(w1, 0);
    quantw_kernel<<<8192, 256>>>(w2, 1);

    for (int s = 0; s < STEPSc; s++) {
        zero_cnt_kernel<<<1, 32>>>();
        route_kernel<<<Tc, 128>>>(comp, temb, s);
        offsets_kernel<<<1, 32>>>();
        ffn1_kernel<<<dim3(32, DFFc/128, Ec), 256>>>();
        ffn2_kernel<<<dim3(32, Dc/128, Ec), 256>>>();
        combine_kernel<<<Tc, 256>>>(comp, nw);
    }

    copy_out_kernel<<<(Tc*Dc + 511)/512, 512>>>(out);
}